// round 7
// baseline (speedup 1.0000x reference)
#include <cuda_runtime.h>
#include <cstdint>

#define HW    3136
#define CIN   1024
#define NT    224      // 14 * 224 = 3136 exactly
#define KC    32
#define NCH   8

// smem (floats): A resident: 8 chunks x 4096 (4 kk-octets x 128 m x 8, swizzled)
//                B: 3-stage ring of [32 k][pitch 232]
#define ASZ      4096
#define A_TOTAL  (NCH * ASZ)            // 32768 floats = 128KB
#define BOFF     A_TOTAL
#define BPITCH   232
#define BSZ      (KC * BPITCH)          // 7424 floats
#define NSTAGE   3
#define SM_FLOATS (BOFF + NSTAGE * BSZ) // 55040
#define SM_BYTES  (SM_FLOATS * 4)       // 220160 bytes

static __device__ __forceinline__ float rna_f(float v) {
    uint32_t o;
    asm("cvt.rna.tf32.f32 %0, %1;" : "=r"(o) : "f"(v));
    return __uint_as_float(o);
}
static __device__ __forceinline__ uint32_t smem_u32(const void* p) {
    uint32_t a;
    asm("{\n\t.reg .u64 t;\n\tcvta.to.shared.u64 t, %1;\n\tcvt.u32.u64 %0, t;\n\t}"
        : "=r"(a) : "l"(p));
    return a;
}
static __device__ __forceinline__ void cp16(uint32_t dst, const void* src) {
    asm volatile("cp.async.cg.shared.global [%0], [%1], 16;" :: "r"(dst), "l"(src) : "memory");
}
static __device__ __forceinline__ void cp_commit() {
    asm volatile("cp.async.commit_group;" ::: "memory");
}
template <int N>
static __device__ __forceinline__ void cp_wait() {
    asm volatile("cp.async.wait_group %0;" :: "n"(N) : "memory");
}

// non-volatile: pure register op, let ptxas schedule/pipeline freely
static __device__ __forceinline__ void mma8(float* c, const float* a, const float* b) {
    asm("mma.sync.aligned.m16n8k8.row.col.f32.tf32.tf32.f32 "
        "{%0,%1,%2,%3}, {%4,%5,%6,%7}, {%8,%9}, {%0,%1,%2,%3};"
        : "+f"(c[0]), "+f"(c[1]), "+f"(c[2]), "+f"(c[3])
        : "r"(__float_as_uint(a[0])), "r"(__float_as_uint(a[1])),
          "r"(__float_as_uint(a[2])), "r"(__float_as_uint(a[3])),
          "r"(__float_as_uint(b[0])), "r"(__float_as_uint(b[1])));
}

__global__ __launch_bounds__(256, 1)
void scc_mma_kernel(const float* __restrict__ x,
                    const float* __restrict__ w,
                    float* __restrict__ out)
{
    extern __shared__ float sm[];
    const uint32_t sb = smem_u32(sm);
    const int tid = threadIdx.x;
    const int lid = tid & 31, wid = tid >> 5;
    const int g = lid >> 2, tg = lid & 3;
    const int r  = blockIdx.x;                 // group fastest: L2 x reuse
    const int p0 = blockIdx.y * NT;
    const int b  = blockIdx.z;
    const float* xb = x + (size_t)b * CIN * HW;

    const int m0 = (wid & 1) * 64;             // 2(M) x 4(N) warp grid, tile 64x56
    const int n0 = (wid >> 1) * 56;

    float acc[4][7][4];
    #pragma unroll
    for (int i = 0; i < 4; i++)
        #pragma unroll
        for (int j = 0; j < 7; j++)
            #pragma unroll
            for (int v = 0; v < 4; v++) acc[i][j][v] = 0.f;

    // ---- B loader: 7 x 16B cp.async per chunk; idx = tid+256*it -> k=idx/56, nq=idx%56
    auto CPA_B = [&](int ch, int stage) {
        const int c0 = (r * 128 + ch * KC) & (CIN - 1);
        const uint32_t bbase = sb + (BOFF + stage * BSZ) * 4;
        #pragma unroll
        for (int it = 0; it < 7; it++) {
            const int idx = tid + 256 * it;
            const int k = idx / 56, nq = idx % 56;
            cp16(bbase + (k * BPITCH + 4 * nq) * 4,
                 xb + (size_t)(c0 + k) * HW + p0 + 4 * nq);
        }
        cp_commit();
    };

    // ---- prologue: start B stages 0,1; load ALL of A (once), rounded + swizzled
    CPA_B(0, 0);
    CPA_B(1, 1);
    {
        const int am = tid & 127;               // m row
        const int ao = (tid >> 7) * 2;          // k-octet base
        const int aswz = 2 * ((am >> 2) & 3);
        const float* wrow = w + (size_t)(r + 8 * am) * 256;
        #pragma unroll
        for (int ch = 0; ch < NCH; ch++) {
            float areg[16];
            #pragma unroll
            for (int o = 0; o < 2; o++) {
                *(float4*)&areg[o * 8 + 0] = *(const float4*)(wrow + ch * KC + (ao + o) * 8);
                *(float4*)&areg[o * 8 + 4] = *(const float4*)(wrow + ch * KC + (ao + o) * 8 + 4);
            }
            float* dstb = sm + ch * ASZ;
            #pragma unroll
            for (int o = 0; o < 2; o++) {
                float* dst = dstb + (ao + o) * 1024 + am * 8;
                #pragma unroll
                for (int c = 0; c < 4; c++)
                    *(float2*)(dst + ((2 * c) ^ aswz)) =
                        make_float2(rna_f(areg[o * 8 + c]), rna_f(areg[o * 8 + c + 4]));
            }
        }
    }
    cp_wait<1>();          // stage 0 landed (stage 1 may still fly)
    __syncthreads();

    // ---- mainloop ----
    #pragma unroll 1
    for (int ch = 0; ch < NCH; ch++) {
        const int stage = ch % NSTAGE;
        if (ch + 2 < NCH) CPA_B(ch + 2, (ch + 2) % NSTAGE);

        const float* Ab = sm + ch * ASZ;
        const float* Bb = sm + BOFF + stage * BSZ;
        #pragma unroll
        for (int kk = 0; kk < 4; kk++) {
            const float* Abk = Ab + kk * 1024;
            const float* Bbk = Bb + kk * 8 * BPITCH;
            float af[4][4], bf[7][2];
            #pragma unroll
            for (int i = 0; i < 4; i++) {
                const int rlo = m0 + 16 * i + g;
                const int rhi = rlo + 8;
                const float2 lo = *(const float2*)(Abk + rlo * 8 + ((2 * tg) ^ (2 * ((rlo >> 2) & 3))));
                const float2 hi = *(const float2*)(Abk + rhi * 8 + ((2 * tg) ^ (2 * ((rhi >> 2) & 3))));
                af[i][0] = lo.x; af[i][1] = hi.x; af[i][2] = lo.y; af[i][3] = hi.y;
            }
            #pragma unroll
            for (int j = 0; j < 7; j++) {
                const int n = n0 + 8 * j + g;
                bf[j][0] = Bbk[tg * BPITCH + n];
                bf[j][1] = Bbk[(tg + 4) * BPITCH + n];
            }
            #pragma unroll
            for (int i = 0; i < 4; i++)
                #pragma unroll
                for (int j = 0; j < 7; j++)
                    mma8(acc[i][j], af[i], bf[j]);
        }

        if (ch + 1 < NCH) {
            if (ch + 2 < NCH) cp_wait<1>();   // ch+1 landed, ch+2 still in flight
            else              cp_wait<0>();   // last: drain
            __syncthreads();
        }
    }

    // ---- epilogue: direct STG, float2 halves (full 32B sectors across quads) ----
    float* ob = out + ((size_t)b * 1024 + r) * HW + p0 + n0 + 2 * tg;
    #pragma unroll
    for (int i = 0; i < 4; i++) {
        const int mlo = m0 + 16 * i + g;
        float* prow = ob + (size_t)(8 * mlo) * HW;
        #pragma unroll
        for (int j = 0; j < 7; j++) {
            *(float2*)(prow + 8 * j) = make_float2(acc[i][j][0], acc[i][j][1]);
            *(float2*)(prow + (size_t)64 * HW + 8 * j) = make_float2(acc[i][j][2], acc[i][j][3]);
        }
    }
}

extern "C" void kernel_launch(void* const* d_in, const int* in_sizes, int n_in,
                              void* d_out, int out_size)
{
    const float* x = (const float*)d_in[0];
    const float* w = (const float*)d_in[1];
    float* out = (float*)d_out;

    cudaFuncSetAttribute(scc_mma_kernel,
                         cudaFuncAttributeMaxDynamicSharedMemorySize, SM_BYTES);
    dim3 grid(8, 14, 16);   // r fastest: adjacent groups share x channels in L2
    scc_mma_kernel<<<grid, 256, SM_BYTES>>>(x, w, out);
}